// round 14
// baseline (speedup 1.0000x reference)
#include <cuda_runtime.h>
#include <cuda_bf16.h>
#include <math.h>

// Problem constants
#define B_    4
#define NTOK  8192
#define DIM_  512
#define H_    8
#define DHEAD 64
#define WS_   256
#define NW    32
#define G_    32
#define KKEEP 179

static __device__ float g_q[(size_t)B_ * H_ * NW * WS_ * DHEAD];     // [bh][w][t][d]
static __device__ float g_k[(size_t)B_ * H_ * NW * WS_ * DHEAD];     // [bh][w][t][d]
static __device__ float g_v[(size_t)B_ * H_ * NW * WS_ * DHEAD];     // [bh][w][d][t] (TRANSPOSED)
static __device__ float g_att[(size_t)B_ * NTOK * DIM_];
static __device__ float g_qmean[(size_t)B_ * H_ * WS_ * DHEAD];
static __device__ float g_kmean[(size_t)B_ * H_ * WS_ * DHEAD];
static __device__ float g_gbias[(size_t)B_ * H_ * WS_];

#define SCALE 0.04419417382415922f   // 512^-0.5

// ---------------------------------------------------------------------------
// tf32 / cp.async helpers
// ---------------------------------------------------------------------------
__device__ __forceinline__ float f2tf_f(float x) {
    unsigned r;
    asm("cvt.rna.tf32.f32 %0, %1;" : "=r"(r) : "f"(x));
    return __uint_as_float(r);
}

__device__ __forceinline__ void mma8(float c[4],
    unsigned a0, unsigned a1, unsigned a2, unsigned a3,
    unsigned b0, unsigned b1)
{
    asm volatile(
        "mma.sync.aligned.m16n8k8.row.col.f32.tf32.tf32.f32 "
        "{%0,%1,%2,%3},{%4,%5,%6,%7},{%8,%9},{%0,%1,%2,%3};"
        : "+f"(c[0]), "+f"(c[1]), "+f"(c[2]), "+f"(c[3])
        : "r"(a0), "r"(a1), "r"(a2), "r"(a3), "r"(b0), "r"(b1));
}

__device__ __forceinline__ void cp16(float* dst_smem, const float* src) {
    unsigned d = (unsigned)__cvta_generic_to_shared(dst_smem);
    asm volatile("cp.async.ca.shared.global [%0], [%1], 16;" :: "r"(d), "l"(src));
}
#define CP_COMMIT() asm volatile("cp.async.commit_group;" ::: "memory")
#define CP_WAIT1()  asm volatile("cp.async.wait_group 1;" ::: "memory")
#define CP_WAIT0()  asm volatile("cp.async.wait_group 0;" ::: "memory")

// ---------------------------------------------------------------------------
// tf32-split GEMM v2: raw-smem + split-at-load + cp.async double buffering.
// Tile 128(M) x 64(N) x 16(K), 512 thr (4m x 4n warps), 2 CTAs/SM.
// Q/K output columns: 3-term. V columns and out GEMM: 2-term.
// EPI 0: qkv scatter (q/k windowed [t][d]; v windowed TRANSPOSED [d][t])
// EPI 1: out = g_att @ w_out + bias
// ---------------------------------------------------------------------------
#define A_STR 20
#define A_BUF (128 * A_STR)
#define B_STR 72
#define B_BUF (16 * B_STR)
#define GEMM_SMEM_FLOATS (2 * A_BUF + 2 * B_BUF)

template<int EPI>
__global__ __launch_bounds__(512, 2) void gemm_tf32_kernel(
    const float* __restrict__ A, const float* __restrict__ Bm,
    const float* __restrict__ bias, float* __restrict__ Cout,
    int N, int K)
{
    extern __shared__ float smg[];
    float* Ar = smg;                 // [2][128][A_STR] raw A ([m][k])
    float* Br = smg + 2 * A_BUF;     // [2][16][B_STR]  raw B ([k][n])

    const int bm = blockIdx.y * 128, bn = blockIdx.x * 64;
    const int tid = threadIdx.x, lane = tid & 31, warp = tid >> 5;
    const int wm = warp >> 2, wn = warp & 3;   // 4 x 4 warp grid

    const float* Ap = (EPI == 0) ? A : g_att;
    const bool two_term = (EPI == 1) || (bn >= 1024);   // V part / out GEMM

    // cp.async loader mapping: every thread 1 A chunk; tid<256 also 1 B chunk
    const int arow = tid >> 2, ach = (tid & 3) << 2;
    const int brow = tid >> 4, bch = (tid & 15) << 2;

    float c_[2][2][4] = {};

    auto issue = [&](int buf, int k0) {
        cp16(&Ar[buf * A_BUF + arow * A_STR + ach],
             Ap + (size_t)(bm + arow) * K + k0 + ach);
        if (tid < 256)
            cp16(&Br[buf * B_BUF + brow * B_STR + bch],
                 Bm + (size_t)(k0 + brow) * N + bn + bch);
    };

    issue(0, 0); CP_COMMIT();
    int buf = 0;
    const int NIT = K / 16;
    for (int it = 0; it < NIT; it++) {
        if (it + 1 < NIT) { issue(buf ^ 1, (it + 1) * 16); CP_COMMIT(); CP_WAIT1(); }
        else CP_WAIT0();
        __syncthreads();

        const float* Ab = Ar + buf * A_BUF;
        const float* Bb = Br + buf * B_BUF;

#pragma unroll
        for (int ks = 0; ks < 2; ks++) {
            const int kb = ks * 8 + (lane & 3);
            unsigned ah[2][4], al[2][4];
#pragma unroll
            for (int mi = 0; mi < 2; mi++) {
                int m = wm * 32 + mi * 16 + (lane >> 2);
                float a0 = Ab[m * A_STR + kb];
                float a1 = Ab[(m + 8) * A_STR + kb];
                float a2 = Ab[m * A_STR + kb + 4];
                float a3 = Ab[(m + 8) * A_STR + kb + 4];
                float h0 = f2tf_f(a0), h1 = f2tf_f(a1), h2 = f2tf_f(a2), h3 = f2tf_f(a3);
                ah[mi][0] = __float_as_uint(h0); al[mi][0] = __float_as_uint(f2tf_f(a0 - h0));
                ah[mi][1] = __float_as_uint(h1); al[mi][1] = __float_as_uint(f2tf_f(a1 - h1));
                ah[mi][2] = __float_as_uint(h2); al[mi][2] = __float_as_uint(f2tf_f(a2 - h2));
                ah[mi][3] = __float_as_uint(h3); al[mi][3] = __float_as_uint(f2tf_f(a3 - h3));
            }
#pragma unroll
            for (int nj = 0; nj < 2; nj++) {
                int n = wn * 16 + nj * 8 + (lane >> 2);
                float br0 = Bb[kb * B_STR + n];
                float br1 = Bb[(kb + 4) * B_STR + n];
                float bh0 = f2tf_f(br0), bh1 = f2tf_f(br1);
                unsigned bhf[2] = {__float_as_uint(bh0), __float_as_uint(bh1)};
                unsigned blf[2] = {__float_as_uint(f2tf_f(br0 - bh0)),
                                   __float_as_uint(f2tf_f(br1 - bh1))};
#pragma unroll
                for (int mi = 0; mi < 2; mi++) {
                    if (!two_term)
                        mma8(c_[mi][nj], ah[mi][0], ah[mi][1], ah[mi][2], ah[mi][3],
                             blf[0], blf[1]);
                    mma8(c_[mi][nj], al[mi][0], al[mi][1], al[mi][2], al[mi][3],
                         bhf[0], bhf[1]);
                    mma8(c_[mi][nj], ah[mi][0], ah[mi][1], ah[mi][2], ah[mi][3],
                         bhf[0], bhf[1]);
                }
            }
        }
        __syncthreads();
        buf ^= 1;
    }

    if (EPI == 0) {
        const int part = bn >> 9;
        float* dst = (part == 0) ? g_q : (part == 1) ? g_k : g_v;
#pragma unroll
        for (int mi = 0; mi < 2; mi++) {
            int mbase = bm + wm * 32 + mi * 16 + (lane >> 2);
#pragma unroll
            for (int nj = 0; nj < 2; nj++) {
                int n = bn + wn * 16 + nj * 8 + ((lane & 3) << 1);
                int head = (n >> 6) & 7, d = n & 63;
#pragma unroll
                for (int half = 0; half < 2; half++) {
                    int m = mbase + half * 8;
                    int b = m >> 13, tok = m & 8191;
                    int w = tok >> 8, t = tok & 255;
                    size_t winb = (((size_t)(b * H_ + head) * NW + w) * (WS_ * DHEAD));
                    if (part == 2) {
                        dst[winb + (size_t)d * WS_ + t]       = c_[mi][nj][half * 2];
                        dst[winb + (size_t)(d + 1) * WS_ + t] = c_[mi][nj][half * 2 + 1];
                    } else {
                        *(float2*)&dst[winb + (size_t)t * DHEAD + d] =
                            make_float2(c_[mi][nj][half * 2], c_[mi][nj][half * 2 + 1]);
                    }
                }
            }
        }
    } else {
#pragma unroll
        for (int mi = 0; mi < 2; mi++) {
            int mbase = bm + wm * 32 + mi * 16 + (lane >> 2);
#pragma unroll
            for (int nj = 0; nj < 2; nj++) {
                int n = bn + wn * 16 + nj * 8 + ((lane & 3) << 1);
                float bx = bias[n], by = bias[n + 1];
#pragma unroll
                for (int half = 0; half < 2; half++) {
                    int m = mbase + half * 8;
                    *(float2*)&Cout[(size_t)m * N + n] =
                        make_float2(c_[mi][nj][half * 2] + bx,
                                    c_[mi][nj][half * 2 + 1] + by);
                }
            }
        }
    }
}

// ---------------------------------------------------------------------------
// Kernel 2: q_mean / k_mean over windows
// ---------------------------------------------------------------------------
__global__ __launch_bounds__(256) void mean_kernel()
{
    int idx = blockIdx.x * 256 + threadIdx.x;
    size_t inner = (size_t)(idx & 16383);
    size_t base = (size_t)(idx >> 14) * ((size_t)NW * 16384) + inner;
    float sq = 0.f, sk = 0.f;
#pragma unroll
    for (int w = 0; w < NW; w++) {
        sq += g_q[base + (size_t)w * 16384];
        sk += g_k[base + (size_t)w * 16384];
    }
    g_qmean[idx] = sq * (1.f / 32.f);
    g_kmean[idx] = sk * (1.f / 32.f);
}

// ---------------------------------------------------------------------------
// Kernel 3: global bias. One block per (b,h).
// ---------------------------------------------------------------------------
#define GLOB_SMEM_FLOATS (256 * 65 + 32 * 64)
__global__ __launch_bounds__(256) void global_kernel(const float* __restrict__ gp)
{
    extern __shared__ float sm[];
    float* km = sm;
    float* gq = sm + 256 * 65;
    const int bh = blockIdx.x;
    const int h = bh & 7;
    const int tid = threadIdx.x;
    const float* kmg = g_kmean + (size_t)bh * 16384;
    const float* qmg = g_qmean + (size_t)bh * 16384;

    for (int i = tid; i < 4096; i += 256) {
        int e = i * 4;
        float4 v = *(const float4*)(kmg + e);
        int t = e >> 6, d = e & 63;
        km[t * 65 + d + 0] = v.x; km[t * 65 + d + 1] = v.y;
        km[t * 65 + d + 2] = v.z; km[t * 65 + d + 3] = v.w;
    }
#pragma unroll
    for (int p = 0; p < 8; p++) {
        int pair = p * 256 + tid;
        int g = pair >> 6, d = pair & 63;
        const float* gprow = gp + ((size_t)h * G_ + g) * WS_;
        float s = 0.f;
        for (int n = 0; n < 256; n++) s += gprow[n] * qmg[n * 64 + d];
        gq[pair] = s;
    }
    __syncthreads();

    int m = tid;
    float bias = 0.f;
    for (int g = 0; g < 32; g++) {
        float s = 0.f;
#pragma unroll
        for (int d = 0; d < 64; d++) s += gq[g * 64 + d] * km[m * 65 + d];
        bias += s;
    }
    g_gbias[(size_t)bh * 256 + m] = bias * SCALE * (1.f / 32.f);
}

// ---------------------------------------------------------------------------
// Kernel 4: fused windowed attention (FROZEN at R12 config: 658us).
// 64 query rows per CTA, 512 thr (4m x 4n). RAW smem, split at fragment load.
// smem 102.7KB -> 2 CTAs/SM. QK 3-term, PV 2-term.
// ---------------------------------------------------------------------------
#define AST  68
#define SST2 260
#define ATTN_SMEM_FLOATS (2 * 64 * AST + 64 * SST2 + 256 + 64)

__global__ __launch_bounds__(512, 2) void attn_kernel(
    const float* __restrict__ lb, const float* __restrict__ gate)
{
    extern __shared__ float sm[];
    float* Qr     = sm;                       // [64][AST] raw Q
    float* KVr    = Qr + 64 * AST;            // [64][AST] raw K/V chunk
    float* S      = KVr + 64 * AST;           // [64][SST2]
    float* gbs    = S + 64 * SST2;            // [256]
    float* rowinv = gbs + 256;                // [64]

    const int tid = threadIdx.x, lane = tid & 31, warp = tid >> 5;
    const int wm = warp >> 2, wn = warp & 3;
    const int chunkQ = blockIdx.x, ww = blockIdx.y, bh = blockIdx.z;
    const int h = bh & 7;
    const size_t win = ((size_t)bh * NW + ww) * (WS_ * DHEAD);
    const int row0 = chunkQ * 64;

    const int srow = tid >> 3;
    const int scol = (tid & 7) << 3;

    *(float4*)&Qr[srow * AST + scol] =
        *(const float4*)(g_q + win + (size_t)row0 * DHEAD + srow * 64 + scol);
    *(float4*)&Qr[srow * AST + scol + 4] =
        *(const float4*)(g_q + win + (size_t)row0 * DHEAD + srow * 64 + scol + 4);
    if (tid < 256) gbs[tid] = g_gbias[(size_t)bh * 256 + tid];
    const float gate_s = 1.f / (1.f + __expf(-__ldg(gate + h)));

    float4 pf0 = *(const float4*)(g_k + win + srow * 64 + scol);
    float4 pf1 = *(const float4*)(g_k + win + srow * 64 + scol + 4);
    __syncthreads();

    for (int c = 0; c < 4; c++) {
        *(float4*)&KVr[srow * AST + scol]     = pf0;
        *(float4*)&KVr[srow * AST + scol + 4] = pf1;
        __syncthreads();
        if (c < 3) {
            size_t o = win + (size_t)(c + 1) * 4096 + srow * 64 + scol;
            pf0 = *(const float4*)(g_k + o);
            pf1 = *(const float4*)(g_k + o + 4);
        }

        float acc[2][4] = {};
#pragma unroll
        for (int ks = 0; ks < 8; ks++) {
            const int kb = ks * 8 + (lane & 3);
            const int m = wm * 16 + (lane >> 2);
            float ar[4];
            ar[0] = Qr[m * AST + kb];
            ar[1] = Qr[(m + 8) * AST + kb];
            ar[2] = Qr[m * AST + kb + 4];
            ar[3] = Qr[(m + 8) * AST + kb + 4];
            unsigned ah[4], al[4];
#pragma unroll
            for (int j = 0; j < 4; j++) {
                float hv = f2tf_f(ar[j]);
                ah[j] = __float_as_uint(hv);
                al[j] = __float_as_uint(f2tf_f(ar[j] - hv));
            }
#pragma unroll
            for (int nj = 0; nj < 2; nj++) {
                int n = wn * 16 + nj * 8 + (lane >> 2);
                float br0 = KVr[n * AST + kb];
                float br1 = KVr[n * AST + kb + 4];
                float bh0 = f2tf_f(br0), bh1 = f2tf_f(br1);
                unsigned bhf[2] = {__float_as_uint(bh0), __float_as_uint(bh1)};
                unsigned blf[2] = {__float_as_uint(f2tf_f(br0 - bh0)),
                                   __float_as_uint(f2tf_f(br1 - bh1))};
                mma8(acc[nj], ah[0], ah[1], ah[2], ah[3], blf[0], blf[1]);
                mma8(acc[nj], al[0], al[1], al[2], al[3], bhf[0], bhf[1]);
                mma8(acc[nj], ah[0], ah[1], ah[2], ah[3], bhf[0], bhf[1]);
            }
        }

#pragma unroll
        for (int nj = 0; nj < 2; nj++) {
            int t = c * 64 + wn * 16 + nj * 8 + ((lane & 3) << 1);
#pragma unroll
            for (int half = 0; half < 2; half++) {
                int qq = wm * 16 + (lane >> 2) + half * 8;
                float2 lb2 = *(const float2*)(lb + ((size_t)h * WS_ + row0 + qq) * WS_ + t);
                float2 o;
                o.x = acc[nj][half * 2] * SCALE + lb2.x + gate_s * gbs[t];
                o.y = acc[nj][half * 2 + 1] * SCALE + lb2.y + gate_s * gbs[t + 1];
                *(float2*)&S[qq * SST2 + t] = o;
            }
        }
        __syncthreads();
    }

    for (int rp = 0; rp < 2; rp++) {
        const int r0 = warp * 4 + rp * 2;
        float vals[2][8];
        unsigned keys[2][8];
#pragma unroll
        for (int s = 0; s < 2; s++)
#pragma unroll
            for (int q = 0; q < 8; q++) {
                float f = S[(r0 + s) * SST2 + q * 32 + lane];
                vals[s][q] = f;
                unsigned u = __float_as_uint(f);
                keys[s][q] = (u & 0x80000000u) ? ~u : (u | 0x80000000u);
            }
        unsigned lo0 = 0u, hi0 = 0xFFFFFFFFu, lo1 = 0u, hi1 = 0xFFFFFFFFu;
        for (int it = 0; it < 32; it++) {
            unsigned m0 = lo0 + ((hi0 - lo0) >> 1);
            unsigned m1 = lo1 + ((hi1 - lo1) >> 1);
            int c0 = 0, c1 = 0;
#pragma unroll
            for (int q = 0; q < 8; q++) {
                c0 += (keys[0][q] >= m0) ? 1 : 0;
                c1 += (keys[1][q] >= m1) ? 1 : 0;
            }
            c0 = __reduce_add_sync(0xffffffffu, c0);
            c1 = __reduce_add_sync(0xffffffffu, c1);
            if (c0 >= KKEEP) lo0 = m0; else hi0 = m0;
            if (c1 >= KKEEP) lo1 = m1; else hi1 = m1;
        }
        unsigned los[2] = {lo0, lo1};
#pragma unroll
        for (int s = 0; s < 2; s++) {
            unsigned mk = 0u;
#pragma unroll
            for (int q = 0; q < 8; q++) mk = max(mk, keys[s][q]);
            mk = __reduce_max_sync(0xffffffffu, mk);
            float mx = (mk & 0x80000000u) ? __uint_as_float(mk ^ 0x80000000u)
                                          : __uint_as_float(~mk);
            float ssum = 0.f;
#pragma unroll
            for (int q = 0; q < 8; q++) {
                float p = (keys[s][q] >= los[s]) ? __expf(vals[s][q] - mx) : 0.f;
                S[(r0 + s) * SST2 + q * 32 + lane] = f2tf_f(p);
                ssum += p;
            }
#pragma unroll
            for (int o = 16; o > 0; o >>= 1) ssum += __shfl_xor_sync(0xffffffffu, ssum, o);
            if (lane == 0) rowinv[r0 + s] = 1.f / ssum;
        }
    }

    pf0 = *(const float4*)(g_v + win + (size_t)srow * WS_ + scol);
    pf1 = *(const float4*)(g_v + win + (size_t)srow * WS_ + scol + 4);
    __syncthreads();

    float acc2[2][4] = {};
    for (int c = 0; c < 4; c++) {
        *(float4*)&KVr[srow * AST + scol]     = pf0;
        *(float4*)&KVr[srow * AST + scol + 4] = pf1;
        __syncthreads();
        if (c < 3) {
            size_t o = win + (size_t)srow * WS_ + (c + 1) * 64 + scol;
            pf0 = *(const float4*)(g_v + o);
            pf1 = *(const float4*)(g_v + o + 4);
        }

#pragma unroll
        for (int ks = 0; ks < 8; ks++) {
            const int kl = ks * 8 + (lane & 3);
            const int kg = c * 64 + kl;
            const int m = wm * 16 + (lane >> 2);
            unsigned ah[4];
            ah[0] = __float_as_uint(S[m * SST2 + kg]);
            ah[1] = __float_as_uint(S[(m + 8) * SST2 + kg]);
            ah[2] = __float_as_uint(S[m * SST2 + kg + 4]);
            ah[3] = __float_as_uint(S[(m + 8) * SST2 + kg + 4]);
#pragma unroll
            for (int nj = 0; nj < 2; nj++) {
                int n = wn * 16 + nj * 8 + (lane >> 2);
                float br0 = KVr[n * AST + kl];
                float br1 = KVr[n * AST + kl + 4];
                float bh0 = f2tf_f(br0), bh1 = f2tf_f(br1);
                unsigned bhf[2] = {__float_as_uint(bh0), __float_as_uint(bh1)};
                unsigned blf[2] = {__float_as_uint(f2tf_f(br0 - bh0)),
                                   __float_as_uint(f2tf_f(br1 - bh1))};
                mma8(acc2[nj], ah[0], ah[1], ah[2], ah[3], blf[0], blf[1]);
                mma8(acc2[nj], ah[0], ah[1], ah[2], ah[3], bhf[0], bhf[1]);
            }
        }
        __syncthreads();
    }

    const int b = bh >> 3;
#pragma unroll
    for (int nj = 0; nj < 2; nj++) {
        int d = wn * 16 + nj * 8 + ((lane & 3) << 1);
#pragma unroll
        for (int half = 0; half < 2; half++) {
            int q = wm * 16 + (lane >> 2) + half * 8;
            float inv = rowinv[q];
            int tok = ww * 256 + row0 + q;
            *(float2*)&g_att[((size_t)b * NTOK + tok) * DIM_ + h * 64 + d] =
                make_float2(acc2[nj][half * 2] * inv,
                            acc2[nj][half * 2 + 1] * inv);
        }
    }
}

// ---------------------------------------------------------------------------
extern "C" void kernel_launch(void* const* d_in, const int* in_sizes, int n_in,
                              void* d_out, int out_size)
{
    const float* x     = (const float*)d_in[0];
    const float* w_qkv = (const float*)d_in[1];
    const float* w_out = (const float*)d_in[2];
    const float* b_out = (const float*)d_in[3];
    const float* lb    = (const float*)d_in[4];
    const float* gp    = (const float*)d_in[5];
    const float* gate  = (const float*)d_in[6];
    float* out = (float*)d_out;

    const int glob_smem = GLOB_SMEM_FLOATS * 4;
    const int attn_smem = ATTN_SMEM_FLOATS * 4;
    const int gemm_smem = GEMM_SMEM_FLOATS * 4;
    cudaFuncSetAttribute(global_kernel, cudaFuncAttributeMaxDynamicSharedMemorySize, glob_smem);
    cudaFuncSetAttribute(attn_kernel, cudaFuncAttributeMaxDynamicSharedMemorySize, attn_smem);
    cudaFuncSetAttribute(gemm_tf32_kernel<0>, cudaFuncAttributeMaxDynamicSharedMemorySize, gemm_smem);
    cudaFuncSetAttribute(gemm_tf32_kernel<1>, cudaFuncAttributeMaxDynamicSharedMemorySize, gemm_smem);

    // qkv GEMM: M=32768, N=1536, K=512 — tiles 128x64
    dim3 g1(1536 / 64, 32768 / 128);
    gemm_tf32_kernel<0><<<g1, 512, gemm_smem>>>(x, w_qkv, nullptr, nullptr, 1536, 512);

    mean_kernel<<<(B_ * H_ * WS_ * DHEAD) / 256, 256>>>();

    global_kernel<<<B_ * H_, 256, glob_smem>>>(gp);

    dim3 g4(4, NW, B_ * H_);
    attn_kernel<<<g4, 512, attn_smem>>>(lb, gate);

    // out GEMM: M=32768, N=512, K=512 — tiles 128x64
    dim3 g5(512 / 64, 32768 / 128);
    gemm_tf32_kernel<1><<<g5, 512, gemm_smem>>>(nullptr, w_out, b_out, out, 512, 512);
}

// round 16
// speedup vs baseline: 1.0956x; 1.0956x over previous
#include <cuda_runtime.h>
#include <cuda_bf16.h>
#include <math.h>

// Problem constants
#define B_    4
#define NTOK  8192
#define DIM_  512
#define H_    8
#define DHEAD 64
#define WS_   256
#define NW    32
#define G_    32
#define KKEEP 179

static __device__ float g_q[(size_t)B_ * H_ * NW * WS_ * DHEAD];     // [bh][w][t][d]
static __device__ float g_k[(size_t)B_ * H_ * NW * WS_ * DHEAD];     // [bh][w][t][d]
static __device__ float g_v[(size_t)B_ * H_ * NW * WS_ * DHEAD];     // [bh][w][d][t] (TRANSPOSED)
static __device__ float g_att[(size_t)B_ * NTOK * DIM_];
static __device__ float g_qmean[(size_t)B_ * H_ * WS_ * DHEAD];
static __device__ float g_kmean[(size_t)B_ * H_ * WS_ * DHEAD];
static __device__ float g_gbias[(size_t)B_ * H_ * WS_];

#define SCALE 0.04419417382415922f   // 512^-0.5

// ---------------------------------------------------------------------------
// tf32 / cp.async helpers
// ---------------------------------------------------------------------------
__device__ __forceinline__ float f2tf_f(float x) {
    unsigned r;
    asm("cvt.rna.tf32.f32 %0, %1;" : "=r"(r) : "f"(x));
    return __uint_as_float(r);
}

__device__ __forceinline__ void mma8(float c[4],
    unsigned a0, unsigned a1, unsigned a2, unsigned a3,
    unsigned b0, unsigned b1)
{
    asm volatile(
        "mma.sync.aligned.m16n8k8.row.col.f32.tf32.tf32.f32 "
        "{%0,%1,%2,%3},{%4,%5,%6,%7},{%8,%9},{%0,%1,%2,%3};"
        : "+f"(c[0]), "+f"(c[1]), "+f"(c[2]), "+f"(c[3])
        : "r"(a0), "r"(a1), "r"(a2), "r"(a3), "r"(b0), "r"(b1));
}

__device__ __forceinline__ void cp16(float* dst_smem, const float* src) {
    unsigned d = (unsigned)__cvta_generic_to_shared(dst_smem);
    asm volatile("cp.async.ca.shared.global [%0], [%1], 16;" :: "r"(d), "l"(src));
}
#define CP_COMMIT() asm volatile("cp.async.commit_group;" ::: "memory")
#define CP_WAIT1()  asm volatile("cp.async.wait_group 1;" ::: "memory")
#define CP_WAIT0()  asm volatile("cp.async.wait_group 0;" ::: "memory")

// ---------------------------------------------------------------------------
// tf32 3-term GEMM v3: 128x128x16 tile (validated intensity), raw fp32 smem,
// split at fragment-load time (validated in attn), cp.async double buffering.
// 512 thr (4x4 warps), launch_bounds(512,2) -> 2 CTAs/SM (smem 37KB, ~56 regs).
// Q/K output columns: 3-term. V columns and out GEMM: 2-term.
// EPI 0: qkv scatter (q/k windowed [t][d]; v windowed TRANSPOSED [d][t])
// EPI 1: out = g_att @ w_out + bias
// ---------------------------------------------------------------------------
#define A_STR 20                  // A word stride: conflict-free ((20m+k)%32 distinct)
#define A_BUF (128 * A_STR)       // 2560 floats
#define B_STR 136                 // B word stride: conflict-free ((136k+n)%32 distinct)
#define B_BUF (16 * B_STR)        // 2176 floats
#define GEMM_SMEM_FLOATS (2 * A_BUF + 2 * B_BUF)   // 9472 floats = 37.9KB

template<int EPI>
__global__ __launch_bounds__(512, 2) void gemm_tf32_kernel(
    const float* __restrict__ A, const float* __restrict__ Bm,
    const float* __restrict__ bias, float* __restrict__ Cout,
    int N, int K)
{
    extern __shared__ float smg[];
    float* Ar = smg;                 // [2][128][A_STR] raw A ([m][k])
    float* Br = smg + 2 * A_BUF;     // [2][16][B_STR]  raw B ([k][n])

    const int bm = blockIdx.y * 128, bn = blockIdx.x * 128;
    const int tid = threadIdx.x, lane = tid & 31, warp = tid >> 5;
    const int wm = warp >> 2, wn = warp & 3;   // 4 x 4 warp grid

    const float* Ap = (EPI == 0) ? A : g_att;
    const bool two_term = (EPI == 1) || (bn >= 1024);   // V part / out GEMM

    // cp.async loader mapping: 512 threads, one float4 of A and one of B each
    const int arow = tid >> 2,  ach = (tid & 3) << 2;   // A: 128 rows x 16 k
    const int brow = tid >> 5,  bch = (tid & 31) << 2;  // B: 16 k x 128 n

    float c_[2][4][4] = {};

    auto issue = [&](int buf, int k0) {
        cp16(&Ar[buf * A_BUF + arow * A_STR + ach],
             Ap + (size_t)(bm + arow) * K + k0 + ach);
        cp16(&Br[buf * B_BUF + brow * B_STR + bch],
             Bm + (size_t)(k0 + brow) * N + bn + bch);
    };

    issue(0, 0); CP_COMMIT();
    int buf = 0;
    const int NIT = K / 16;
    for (int it = 0; it < NIT; it++) {
        if (it + 1 < NIT) { issue(buf ^ 1, (it + 1) * 16); CP_COMMIT(); CP_WAIT1(); }
        else CP_WAIT0();
        __syncthreads();

        const float* Ab = Ar + buf * A_BUF;
        const float* Bb = Br + buf * B_BUF;

#pragma unroll
        for (int ks = 0; ks < 2; ks++) {
            const int kb = ks * 8 + (lane & 3);
            unsigned ah[2][4], al[2][4];
#pragma unroll
            for (int mi = 0; mi < 2; mi++) {
                int m = wm * 32 + mi * 16 + (lane >> 2);
                float a0 = Ab[m * A_STR + kb];
                float a1 = Ab[(m + 8) * A_STR + kb];
                float a2 = Ab[m * A_STR + kb + 4];
                float a3 = Ab[(m + 8) * A_STR + kb + 4];
                float h0 = f2tf_f(a0), h1 = f2tf_f(a1), h2 = f2tf_f(a2), h3 = f2tf_f(a3);
                ah[mi][0] = __float_as_uint(h0); al[mi][0] = __float_as_uint(f2tf_f(a0 - h0));
                ah[mi][1] = __float_as_uint(h1); al[mi][1] = __float_as_uint(f2tf_f(a1 - h1));
                ah[mi][2] = __float_as_uint(h2); al[mi][2] = __float_as_uint(f2tf_f(a2 - h2));
                ah[mi][3] = __float_as_uint(h3); al[mi][3] = __float_as_uint(f2tf_f(a3 - h3));
            }
#pragma unroll
            for (int nj = 0; nj < 4; nj++) {
                int n = wn * 32 + nj * 8 + (lane >> 2);
                float br0 = Bb[kb * B_STR + n];
                float br1 = Bb[(kb + 4) * B_STR + n];
                float bh0 = f2tf_f(br0), bh1 = f2tf_f(br1);
                unsigned bhf[2] = {__float_as_uint(bh0), __float_as_uint(bh1)};
                unsigned blf[2] = {__float_as_uint(f2tf_f(br0 - bh0)),
                                   __float_as_uint(f2tf_f(br1 - bh1))};
#pragma unroll
                for (int mi = 0; mi < 2; mi++) {
                    if (!two_term)
                        mma8(c_[mi][nj], ah[mi][0], ah[mi][1], ah[mi][2], ah[mi][3],
                             blf[0], blf[1]);
                    mma8(c_[mi][nj], al[mi][0], al[mi][1], al[mi][2], al[mi][3],
                         bhf[0], bhf[1]);
                    mma8(c_[mi][nj], ah[mi][0], ah[mi][1], ah[mi][2], ah[mi][3],
                         bhf[0], bhf[1]);
                }
            }
        }
        __syncthreads();
        buf ^= 1;
    }

    if (EPI == 0) {
        const int part = bn >> 9;
        float* dst = (part == 0) ? g_q : (part == 1) ? g_k : g_v;
#pragma unroll
        for (int mi = 0; mi < 2; mi++) {
            int mbase = bm + wm * 32 + mi * 16 + (lane >> 2);
#pragma unroll
            for (int nj = 0; nj < 4; nj++) {
                int n = bn + wn * 32 + nj * 8 + ((lane & 3) << 1);
                int head = (n >> 6) & 7, d = n & 63;
#pragma unroll
                for (int half = 0; half < 2; half++) {
                    int m = mbase + half * 8;
                    int b = m >> 13, tok = m & 8191;
                    int w = tok >> 8, t = tok & 255;
                    size_t winb = (((size_t)(b * H_ + head) * NW + w) * (WS_ * DHEAD));
                    if (part == 2) {
                        dst[winb + (size_t)d * WS_ + t]       = c_[mi][nj][half * 2];
                        dst[winb + (size_t)(d + 1) * WS_ + t] = c_[mi][nj][half * 2 + 1];
                    } else {
                        *(float2*)&dst[winb + (size_t)t * DHEAD + d] =
                            make_float2(c_[mi][nj][half * 2], c_[mi][nj][half * 2 + 1]);
                    }
                }
            }
        }
    } else {
#pragma unroll
        for (int mi = 0; mi < 2; mi++) {
            int mbase = bm + wm * 32 + mi * 16 + (lane >> 2);
#pragma unroll
            for (int nj = 0; nj < 4; nj++) {
                int n = bn + wn * 32 + nj * 8 + ((lane & 3) << 1);
                float bx = bias[n], by = bias[n + 1];
#pragma unroll
                for (int half = 0; half < 2; half++) {
                    int m = mbase + half * 8;
                    *(float2*)&Cout[(size_t)m * N + n] =
                        make_float2(c_[mi][nj][half * 2] + bx,
                                    c_[mi][nj][half * 2 + 1] + by);
                }
            }
        }
    }
}

// ---------------------------------------------------------------------------
// Kernel 2: q_mean / k_mean over windows
// ---------------------------------------------------------------------------
__global__ __launch_bounds__(256) void mean_kernel()
{
    int idx = blockIdx.x * 256 + threadIdx.x;
    size_t inner = (size_t)(idx & 16383);
    size_t base = (size_t)(idx >> 14) * ((size_t)NW * 16384) + inner;
    float sq = 0.f, sk = 0.f;
#pragma unroll
    for (int w = 0; w < NW; w++) {
        sq += g_q[base + (size_t)w * 16384];
        sk += g_k[base + (size_t)w * 16384];
    }
    g_qmean[idx] = sq * (1.f / 32.f);
    g_kmean[idx] = sk * (1.f / 32.f);
}

// ---------------------------------------------------------------------------
// Kernel 3: global bias. One block per (b,h).
// ---------------------------------------------------------------------------
#define GLOB_SMEM_FLOATS (256 * 65 + 32 * 64)
__global__ __launch_bounds__(256) void global_kernel(const float* __restrict__ gp)
{
    extern __shared__ float sm[];
    float* km = sm;
    float* gq = sm + 256 * 65;
    const int bh = blockIdx.x;
    const int h = bh & 7;
    const int tid = threadIdx.x;
    const float* kmg = g_kmean + (size_t)bh * 16384;
    const float* qmg = g_qmean + (size_t)bh * 16384;

    for (int i = tid; i < 4096; i += 256) {
        int e = i * 4;
        float4 v = *(const float4*)(kmg + e);
        int t = e >> 6, d = e & 63;
        km[t * 65 + d + 0] = v.x; km[t * 65 + d + 1] = v.y;
        km[t * 65 + d + 2] = v.z; km[t * 65 + d + 3] = v.w;
    }
#pragma unroll
    for (int p = 0; p < 8; p++) {
        int pair = p * 256 + tid;
        int g = pair >> 6, d = pair & 63;
        const float* gprow = gp + ((size_t)h * G_ + g) * WS_;
        float s = 0.f;
        for (int n = 0; n < 256; n++) s += gprow[n] * qmg[n * 64 + d];
        gq[pair] = s;
    }
    __syncthreads();

    int m = tid;
    float bias = 0.f;
    for (int g = 0; g < 32; g++) {
        float s = 0.f;
#pragma unroll
        for (int d = 0; d < 64; d++) s += gq[g * 64 + d] * km[m * 65 + d];
        bias += s;
    }
    g_gbias[(size_t)bh * 256 + m] = bias * SCALE * (1.f / 32.f);
}

// ---------------------------------------------------------------------------
// Kernel 4: fused windowed attention (FROZEN at R12 config: 658us).
// 64 query rows per CTA, 512 thr (4m x 4n). RAW smem, split at fragment load.
// smem 102.7KB -> 2 CTAs/SM. QK 3-term tf32, PV 2-term tf32.
// ---------------------------------------------------------------------------
#define AST  68
#define SST2 260
#define ATTN_SMEM_FLOATS (2 * 64 * AST + 64 * SST2 + 256 + 64)

__global__ __launch_bounds__(512, 2) void attn_kernel(
    const float* __restrict__ lb, const float* __restrict__ gate)
{
    extern __shared__ float sm[];
    float* Qr     = sm;                       // [64][AST] raw Q
    float* KVr    = Qr + 64 * AST;            // [64][AST] raw K/V chunk
    float* S      = KVr + 64 * AST;           // [64][SST2]
    float* gbs    = S + 64 * SST2;            // [256]
    float* rowinv = gbs + 256;                // [64]

    const int tid = threadIdx.x, lane = tid & 31, warp = tid >> 5;
    const int wm = warp >> 2, wn = warp & 3;
    const int chunkQ = blockIdx.x, ww = blockIdx.y, bh = blockIdx.z;
    const int h = bh & 7;
    const size_t win = ((size_t)bh * NW + ww) * (WS_ * DHEAD);
    const int row0 = chunkQ * 64;

    const int srow = tid >> 3;
    const int scol = (tid & 7) << 3;

    *(float4*)&Qr[srow * AST + scol] =
        *(const float4*)(g_q + win + (size_t)row0 * DHEAD + srow * 64 + scol);
    *(float4*)&Qr[srow * AST + scol + 4] =
        *(const float4*)(g_q + win + (size_t)row0 * DHEAD + srow * 64 + scol + 4);
    if (tid < 256) gbs[tid] = g_gbias[(size_t)bh * 256 + tid];
    const float gate_s = 1.f / (1.f + __expf(-__ldg(gate + h)));

    float4 pf0 = *(const float4*)(g_k + win + srow * 64 + scol);
    float4 pf1 = *(const float4*)(g_k + win + srow * 64 + scol + 4);
    __syncthreads();

    for (int c = 0; c < 4; c++) {
        *(float4*)&KVr[srow * AST + scol]     = pf0;
        *(float4*)&KVr[srow * AST + scol + 4] = pf1;
        __syncthreads();
        if (c < 3) {
            size_t o = win + (size_t)(c + 1) * 4096 + srow * 64 + scol;
            pf0 = *(const float4*)(g_k + o);
            pf1 = *(const float4*)(g_k + o + 4);
        }

        float acc[2][4] = {};
#pragma unroll
        for (int ks = 0; ks < 8; ks++) {
            const int kb = ks * 8 + (lane & 3);
            const int m = wm * 16 + (lane >> 2);
            float ar[4];
            ar[0] = Qr[m * AST + kb];
            ar[1] = Qr[(m + 8) * AST + kb];
            ar[2] = Qr[m * AST + kb + 4];
            ar[3] = Qr[(m + 8) * AST + kb + 4];
            unsigned ah[4], al[4];
#pragma unroll
            for (int j = 0; j < 4; j++) {
                float hv = f2tf_f(ar[j]);
                ah[j] = __float_as_uint(hv);
                al[j] = __float_as_uint(f2tf_f(ar[j] - hv));
            }
#pragma unroll
            for (int nj = 0; nj < 2; nj++) {
                int n = wn * 16 + nj * 8 + (lane >> 2);
                float br0 = KVr[n * AST + kb];
                float br1 = KVr[n * AST + kb + 4];
                float bh0 = f2tf_f(br0), bh1 = f2tf_f(br1);
                unsigned bhf[2] = {__float_as_uint(bh0), __float_as_uint(bh1)};
                unsigned blf[2] = {__float_as_uint(f2tf_f(br0 - bh0)),
                                   __float_as_uint(f2tf_f(br1 - bh1))};
                mma8(acc[nj], ah[0], ah[1], ah[2], ah[3], blf[0], blf[1]);
                mma8(acc[nj], al[0], al[1], al[2], al[3], bhf[0], bhf[1]);
                mma8(acc[nj], ah[0], ah[1], ah[2], ah[3], bhf[0], bhf[1]);
            }
        }

#pragma unroll
        for (int nj = 0; nj < 2; nj++) {
            int t = c * 64 + wn * 16 + nj * 8 + ((lane & 3) << 1);
#pragma unroll
            for (int half = 0; half < 2; half++) {
                int qq = wm * 16 + (lane >> 2) + half * 8;
                float2 lb2 = *(const float2*)(lb + ((size_t)h * WS_ + row0 + qq) * WS_ + t);
                float2 o;
                o.x = acc[nj][half * 2] * SCALE + lb2.x + gate_s * gbs[t];
                o.y = acc[nj][half * 2 + 1] * SCALE + lb2.y + gate_s * gbs[t + 1];
                *(float2*)&S[qq * SST2 + t] = o;
            }
        }
        __syncthreads();
    }

    for (int rp = 0; rp < 2; rp++) {
        const int r0 = warp * 4 + rp * 2;
        float vals[2][8];
        unsigned keys[2][8];
#pragma unroll
        for (int s = 0; s < 2; s++)
#pragma unroll
            for (int q = 0; q < 8; q++) {
                float f = S[(r0 + s) * SST2 + q * 32 + lane];
                vals[s][q] = f;
                unsigned u = __float_as_uint(f);
                keys[s][q] = (u & 0x80000000u) ? ~u : (u | 0x80000000u);
            }
        unsigned lo0 = 0u, hi0 = 0xFFFFFFFFu, lo1 = 0u, hi1 = 0xFFFFFFFFu;
        for (int it = 0; it < 32; it++) {
            unsigned m0 = lo0 + ((hi0 - lo0) >> 1);
            unsigned m1 = lo1 + ((hi1 - lo1) >> 1);
            int c0 = 0, c1 = 0;
#pragma unroll
            for (int q = 0; q < 8; q++) {
                c0 += (keys[0][q] >= m0) ? 1 : 0;
                c1 += (keys[1][q] >= m1) ? 1 : 0;
            }
            c0 = __reduce_add_sync(0xffffffffu, c0);
            c1 = __reduce_add_sync(0xffffffffu, c1);
            if (c0 >= KKEEP) lo0 = m0; else hi0 = m0;
            if (c1 >= KKEEP) lo1 = m1; else hi1 = m1;
        }
        unsigned los[2] = {lo0, lo1};
#pragma unroll
        for (int s = 0; s < 2; s++) {
            unsigned mk = 0u;
#pragma unroll
            for (int q = 0; q < 8; q++) mk = max(mk, keys[s][q]);
            mk = __reduce_max_sync(0xffffffffu, mk);
            float mx = (mk & 0x80000000u) ? __uint_as_float(mk ^ 0x80000000u)
                                          : __uint_as_float(~mk);
            float ssum = 0.f;
#pragma unroll
            for (int q = 0; q < 8; q++) {
                float p = (keys[s][q] >= los[s]) ? __expf(vals[s][q] - mx) : 0.f;
                S[(r0 + s) * SST2 + q * 32 + lane] = f2tf_f(p);
                ssum += p;
            }
#pragma unroll
            for (int o = 16; o > 0; o >>= 1) ssum += __shfl_xor_sync(0xffffffffu, ssum, o);
            if (lane == 0) rowinv[r0 + s] = 1.f / ssum;
        }
    }

    pf0 = *(const float4*)(g_v + win + (size_t)srow * WS_ + scol);
    pf1 = *(const float4*)(g_v + win + (size_t)srow * WS_ + scol + 4);
    __syncthreads();

    float acc2[2][4] = {};
    for (int c = 0; c < 4; c++) {
        *(float4*)&KVr[srow * AST + scol]     = pf0;
        *(float4*)&KVr[srow * AST + scol + 4] = pf1;
        __syncthreads();
        if (c < 3) {
            size_t o = win + (size_t)srow * WS_ + (c + 1) * 64 + scol;
            pf0 = *(const float4*)(g_v + o);
            pf1 = *(const float4*)(g_v + o + 4);
        }

#pragma unroll
        for (int ks = 0; ks < 8; ks++) {
            const int kl = ks * 8 + (lane & 3);
            const int kg = c * 64 + kl;
            const int m = wm * 16 + (lane >> 2);
            unsigned ah[4];
            ah[0] = __float_as_uint(S[m * SST2 + kg]);
            ah[1] = __float_as_uint(S[(m + 8) * SST2 + kg]);
            ah[2] = __float_as_uint(S[m * SST2 + kg + 4]);
            ah[3] = __float_as_uint(S[(m + 8) * SST2 + kg + 4]);
#pragma unroll
            for (int nj = 0; nj < 2; nj++) {
                int n = wn * 16 + nj * 8 + (lane >> 2);
                float br0 = KVr[n * AST + kl];
                float br1 = KVr[n * AST + kl + 4];
                float bh0 = f2tf_f(br0), bh1 = f2tf_f(br1);
                unsigned bhf[2] = {__float_as_uint(bh0), __float_as_uint(bh1)};
                unsigned blf[2] = {__float_as_uint(f2tf_f(br0 - bh0)),
                                   __float_as_uint(f2tf_f(br1 - bh1))};
                mma8(acc2[nj], ah[0], ah[1], ah[2], ah[3], blf[0], blf[1]);
                mma8(acc2[nj], ah[0], ah[1], ah[2], ah[3], bhf[0], bhf[1]);
            }
        }
        __syncthreads();
    }

    const int b = bh >> 3;
#pragma unroll
    for (int nj = 0; nj < 2; nj++) {
        int d = wn * 16 + nj * 8 + ((lane & 3) << 1);
#pragma unroll
        for (int half = 0; half < 2; half++) {
            int q = wm * 16 + (lane >> 2) + half * 8;
            float inv = rowinv[q];
            int tok = ww * 256 + row0 + q;
            *(float2*)&g_att[((size_t)b * NTOK + tok) * DIM_ + h * 64 + d] =
                make_float2(acc2[nj][half * 2] * inv,
                            acc2[nj][half * 2 + 1] * inv);
        }
    }
}

// ---------------------------------------------------------------------------
extern "C" void kernel_launch(void* const* d_in, const int* in_sizes, int n_in,
                              void* d_out, int out_size)
{
    const float* x     = (const float*)d_in[0];
    const float* w_qkv = (const float*)d_in[1];
    const float* w_out = (const float*)d_in[2];
    const float* b_out = (const float*)d_in[3];
    const float* lb    = (const float*)d_in[4];
    const float* gp    = (const float*)d_in[5];
    const float* gate  = (const float*)d_in[6];
    float* out = (float*)d_out;

    const int glob_smem = GLOB_SMEM_FLOATS * 4;
    const int attn_smem = ATTN_SMEM_FLOATS * 4;
    const int gemm_smem = GEMM_SMEM_FLOATS * 4;
    cudaFuncSetAttribute(global_kernel, cudaFuncAttributeMaxDynamicSharedMemorySize, glob_smem);
    cudaFuncSetAttribute(attn_kernel, cudaFuncAttributeMaxDynamicSharedMemorySize, attn_smem);
    cudaFuncSetAttribute(gemm_tf32_kernel<0>, cudaFuncAttributeMaxDynamicSharedMemorySize, gemm_smem);
    cudaFuncSetAttribute(gemm_tf32_kernel<1>, cudaFuncAttributeMaxDynamicSharedMemorySize, gemm_smem);

    // qkv GEMM: M=32768, N=1536, K=512 (tf32 3-term, 128x128 tile, cp.async)
    dim3 g1(1536 / 128, 32768 / 128);
    gemm_tf32_kernel<0><<<g1, 512, gemm_smem>>>(x, w_qkv, nullptr, nullptr, 1536, 512);

    mean_kernel<<<(B_ * H_ * WS_ * DHEAD) / 256, 256>>>();

    global_kernel<<<B_ * H_, 256, glob_smem>>>(gp);

    dim3 g4(4, NW, B_ * H_);
    attn_kernel<<<g4, 512, attn_smem>>>(lb, gate);

    // out GEMM: M=32768, N=512, K=512 (2-term)
    dim3 g5(512 / 128, 32768 / 128);
    gemm_tf32_kernel<1><<<g5, 512, gemm_smem>>>(nullptr, w_out, b_out, out, 512, 512);
}